// round 9
// baseline (speedup 1.0000x reference)
#include <cuda_runtime.h>
#include <cuda_bf16.h>
#include <cuda_fp16.h>

#define N_NODES 100000
#define DIM 128
#define MAX_EDGES 1700000
#define SCAN_CHUNK 512
#define N_CHUNKS ((N_NODES + SCAN_CHUNK - 1) / SCAN_CHUNK)   // 196
#define ECHUNK 32                                            // edges per 16-lane group

// ---------------------------------------------------------------------------
// Scratch (allocation-free rule: device globals)
// ---------------------------------------------------------------------------
__device__ __half g_h[N_NODES * DIM];         // h = x @ W^T  (fp16)
__device__ __half g_Wh[DIM * DIM];            // W in fp16
__device__ int    g_cnt[N_NODES];
__device__ int    g_rowstart[N_NODES + 1];
__device__ int    g_cursor[N_NODES];
__device__ int    g_blocksum[N_CHUNKS];
__device__ int4   g_edge4[MAX_EDGES];         // {col, val-bits, row, 0} sorted by row

// ---------------------------------------------------------------------------
__global__ void k_prep_w(const float* __restrict__ W) {
    int idx = blockIdx.x * blockDim.x + threadIdx.x;
    if (idx < DIM * DIM) g_Wh[idx] = __float2half_rn(W[idx]);
}

// ---------------------------------------------------------------------------
// GEMM via HMMA (unchanged — proven, hidden under binning branch)
// ---------------------------------------------------------------------------
#define SSTRIDE 136

__global__ void __launch_bounds__(256) k_gemm(const float* __restrict__ x) {
    __shared__ __half sA[32 * SSTRIDE];
    __shared__ __half sB[DIM * SSTRIDE];

    const int tid  = threadIdx.x;
    const int row0 = blockIdx.x * 32;

    const uint4* w4 = reinterpret_cast<const uint4*>(g_Wh);
    #pragma unroll
    for (int i = tid; i < 2048; i += 256) {
        int r = i >> 4, cg = i & 15;
        *reinterpret_cast<uint4*>(&sB[r * SSTRIDE + cg * 8]) = w4[i];
    }
    const float4* x4 = reinterpret_cast<const float4*>(x + (size_t)row0 * DIM);
    #pragma unroll
    for (int i = tid; i < 1024; i += 256) {
        float4 v = x4[i];
        int r = i >> 5, k4 = i & 31;
        __half2 p0 = __floats2half2_rn(v.x, v.y);
        __half2 p1 = __floats2half2_rn(v.z, v.w);
        __half* d = &sA[r * SSTRIDE + k4 * 4];
        *reinterpret_cast<__half2*>(d)     = p0;
        *reinterpret_cast<__half2*>(d + 2) = p1;
    }
    __syncthreads();

    const int warp = tid >> 5, lane = tid & 31;
    const int wr = (warp & 1) * 16;
    const int wc = (warp >> 1) * 32;
    const int qr = lane >> 2, qc = lane & 3;

    float c[4][4];
    #pragma unroll
    for (int nc = 0; nc < 4; nc++)
        #pragma unroll
        for (int j = 0; j < 4; j++) c[nc][j] = 0.f;

    #pragma unroll
    for (int ks = 0; ks < 8; ks++) {
        const int k0 = ks * 16 + qc * 2;
        const __half* A0 = &sA[(wr + qr) * SSTRIDE + k0];
        const __half* A8 = A0 + 8 * SSTRIDE;
        unsigned a0 = *reinterpret_cast<const unsigned*>(A0);
        unsigned a1 = *reinterpret_cast<const unsigned*>(A8);
        unsigned a2 = *reinterpret_cast<const unsigned*>(A0 + 8);
        unsigned a3 = *reinterpret_cast<const unsigned*>(A8 + 8);
        #pragma unroll
        for (int nc = 0; nc < 4; nc++) {
            const int n = wc + nc * 8 + qr;
            const __half* B0 = &sB[n * SSTRIDE + k0];
            unsigned b0 = *reinterpret_cast<const unsigned*>(B0);
            unsigned b1 = *reinterpret_cast<const unsigned*>(B0 + 8);
            asm("mma.sync.aligned.m16n8k16.row.col.f32.f16.f16.f32 "
                "{%0,%1,%2,%3}, {%4,%5,%6,%7}, {%8,%9}, {%0,%1,%2,%3};"
                : "+f"(c[nc][0]), "+f"(c[nc][1]), "+f"(c[nc][2]), "+f"(c[nc][3])
                : "r"(a0), "r"(a1), "r"(a2), "r"(a3), "r"(b0), "r"(b1));
        }
    }

    const int r0g = row0 + wr + qr;
    #pragma unroll
    for (int nc = 0; nc < 4; nc++) {
        const int col = wc + nc * 8 + qc * 2;
        __half2 lo = __floats2half2_rn(c[nc][0], c[nc][1]);
        __half2 hi = __floats2half2_rn(c[nc][2], c[nc][3]);
        *reinterpret_cast<__half2*>(&g_h[(size_t)r0g * DIM + col])       = lo;
        *reinterpret_cast<__half2*>(&g_h[(size_t)(r0g + 8) * DIM + col]) = hi;
    }
}

// ---------------------------------------------------------------------------
__global__ void k_zero_cnt() {
    int i = blockIdx.x * blockDim.x + threadIdx.x;
    if (i < N_NODES) g_cnt[i] = 0;
}

// Phase 1: histogram of rows (L2-atomic bound; at floor — leave as-is)
__global__ void k_hist(const int* __restrict__ erow, int n_edges) {
    int t  = blockIdx.x * blockDim.x + threadIdx.x;
    int e4 = n_edges >> 2;
    if (t < e4) {
        int4 r = reinterpret_cast<const int4*>(erow)[t];
        atomicAdd(&g_cnt[r.x], 1);
        atomicAdd(&g_cnt[r.y], 1);
        atomicAdd(&g_cnt[r.z], 1);
        atomicAdd(&g_cnt[r.w], 1);
    } else {
        int e = e4 * 4 + (t - e4);
        if (e < n_edges) atomicAdd(&g_cnt[erow[e]], 1);
    }
}

// ---------------------------------------------------------------------------
__global__ void __launch_bounds__(SCAN_CHUNK) k_scan1() {
    __shared__ int wsum[SCAN_CHUNK / 32];
    int tid  = threadIdx.x;
    int gidx = blockIdx.x * SCAN_CHUNK + tid;
    int v    = (gidx < N_NODES) ? g_cnt[gidx] : 0;

    int lane = tid & 31, wid = tid >> 5;
    int incl = v;
    #pragma unroll
    for (int d = 1; d < 32; d <<= 1) {
        int t = __shfl_up_sync(0xffffffff, incl, d);
        if (lane >= d) incl += t;
    }
    if (lane == 31) wsum[wid] = incl;
    __syncthreads();
    if (wid == 0) {
        int w = (lane < SCAN_CHUNK / 32) ? wsum[lane] : 0;
        int wi = w;
        #pragma unroll
        for (int d = 1; d < 32; d <<= 1) {
            int t = __shfl_up_sync(0xffffffff, wi, d);
            if (lane >= d) wi += t;
        }
        if (lane < SCAN_CHUNK / 32) wsum[lane] = wi - w;
    }
    __syncthreads();
    int excl = incl - v + wsum[wid];
    if (gidx < N_NODES) g_cnt[gidx] = excl;
    if (tid == SCAN_CHUNK - 1) g_blocksum[blockIdx.x] = excl + v;
}

__global__ void __launch_bounds__(256) k_scan2() {
    __shared__ int wsum[8];
    int tid = threadIdx.x;
    int v   = (tid < N_CHUNKS) ? g_blocksum[tid] : 0;
    int lane = tid & 31, wid = tid >> 5;
    int incl = v;
    #pragma unroll
    for (int d = 1; d < 32; d <<= 1) {
        int t = __shfl_up_sync(0xffffffff, incl, d);
        if (lane >= d) incl += t;
    }
    if (lane == 31) wsum[wid] = incl;
    __syncthreads();
    if (wid == 0) {
        int w = (lane < 8) ? wsum[lane] : 0;
        int wi = w;
        #pragma unroll
        for (int d = 1; d < 32; d <<= 1) {
            int t = __shfl_up_sync(0xffffffff, wi, d);
            if (lane >= d) wi += t;
        }
        if (lane < 8) wsum[lane] = wi - w;
    }
    __syncthreads();
    if (tid < N_CHUNKS) g_blocksum[tid] = incl - v + wsum[wid];
}

__global__ void k_scan3(int n_edges) {
    int i = blockIdx.x * blockDim.x + threadIdx.x;
    if (i < N_NODES) {
        int rs = g_cnt[i] + g_blocksum[i / SCAN_CHUNK];
        g_rowstart[i] = rs;
        g_cursor[i]   = rs;
    }
    if (i == 0) g_rowstart[N_NODES] = n_edges;
}

// Phase 3: place — 4 edges per thread; record {col, val, row} per edge
__global__ void k_place(const int*   __restrict__ erow,
                        const int*   __restrict__ ecol,
                        const float* __restrict__ eval,
                        int n_edges) {
    int t  = blockIdx.x * blockDim.x + threadIdx.x;
    int e4 = n_edges >> 2;
    if (t < e4) {
        int4   r = reinterpret_cast<const int4*>(erow)[t];
        int4   c = reinterpret_cast<const int4*>(ecol)[t];
        float4 v = reinterpret_cast<const float4*>(eval)[t];
        int p0 = atomicAdd(&g_cursor[r.x], 1);
        int p1 = atomicAdd(&g_cursor[r.y], 1);
        int p2 = atomicAdd(&g_cursor[r.z], 1);
        int p3 = atomicAdd(&g_cursor[r.w], 1);
        g_edge4[p0] = make_int4(c.x, __float_as_int(v.x), r.x, 0);
        g_edge4[p1] = make_int4(c.y, __float_as_int(v.y), r.y, 0);
        g_edge4[p2] = make_int4(c.z, __float_as_int(v.z), r.z, 0);
        g_edge4[p3] = make_int4(c.w, __float_as_int(v.w), r.w, 0);
    } else {
        int e = e4 * 4 + (t - e4);
        if (e < n_edges) {
            int r = erow[e];
            int pos = atomicAdd(&g_cursor[r], 1);
            g_edge4[pos] = make_int4(ecol[e], __float_as_int(eval[e]), r, 0);
        }
    }
}

// ---------------------------------------------------------------------------
// Phase 4: segmented scan over sorted edges. Each 16-lane group owns a fixed
// ECHUNK-edge slice: uniform trip count (no divergence), perfect balance,
// full 512B per warp LDG.128. Row-change -> atomic vec4 flush (rare: ~150K).
// ---------------------------------------------------------------------------
__device__ __forceinline__ void seg_acc(float4& lo, float4& hi, uint4 p, float v) {
    float2 f0 = __half22float2(*reinterpret_cast<__half2*>(&p.x));
    float2 f1 = __half22float2(*reinterpret_cast<__half2*>(&p.y));
    float2 f2 = __half22float2(*reinterpret_cast<__half2*>(&p.z));
    float2 f3 = __half22float2(*reinterpret_cast<__half2*>(&p.w));
    lo.x += v * f0.x; lo.y += v * f0.y; lo.z += v * f1.x; lo.w += v * f1.y;
    hi.x += v * f2.x; hi.y += v * f2.y; hi.z += v * f3.x; hi.w += v * f3.y;
}

__device__ __forceinline__ void seg_flush(float* __restrict__ out, int row, int sl,
                                          float4 lo, float4 hi) {
    float* op = out + (size_t)row * DIM + sl * 8;
    asm volatile("red.global.add.v4.f32 [%0], {%1,%2,%3,%4};"
                 :: "l"(op), "f"(lo.x), "f"(lo.y), "f"(lo.z), "f"(lo.w) : "memory");
    asm volatile("red.global.add.v4.f32 [%0], {%1,%2,%3,%4};"
                 :: "l"(op + 4), "f"(hi.x), "f"(hi.y), "f"(hi.z), "f"(hi.w) : "memory");
}

__global__ void __launch_bounds__(128) k_segscatter(float* __restrict__ out,
                                                    int n_edges) {
    int grp = blockIdx.x * 8 + (threadIdx.x >> 4);
    int sl  = threadIdx.x & 15;
    int beg = grp * ECHUNK;
    if (beg >= n_edges) return;
    int end = min(beg + ECHUNK, n_edges);

    const uint4* hh = reinterpret_cast<const uint4*>(g_h);   // 16 x 16B per h row

    float4 lo = make_float4(0.f, 0.f, 0.f, 0.f);
    float4 hi = make_float4(0.f, 0.f, 0.f, 0.f);
    int cur = g_edge4[beg].z;

    int e = beg;
    while (e < end) {
        if (e + 4 <= end) {
            int4 m0 = g_edge4[e + 0];
            int4 m1 = g_edge4[e + 1];
            int4 m2 = g_edge4[e + 2];
            int4 m3 = g_edge4[e + 3];
            if ((m0.z == cur) & (m1.z == cur) & (m2.z == cur) & (m3.z == cur)) {
                // fast path: 4 independent gathers in flight
                uint4 p0 = hh[(size_t)m0.x * 16 + sl];
                uint4 p1 = hh[(size_t)m1.x * 16 + sl];
                uint4 p2 = hh[(size_t)m2.x * 16 + sl];
                uint4 p3 = hh[(size_t)m3.x * 16 + sl];
                seg_acc(lo, hi, p0, __int_as_float(m0.y));
                seg_acc(lo, hi, p1, __int_as_float(m1.y));
                seg_acc(lo, hi, p2, __int_as_float(m2.y));
                seg_acc(lo, hi, p3, __int_as_float(m3.y));
                e += 4;
                continue;
            }
            // slow path: single edge (row may change)
            if (m0.z != cur) {
                seg_flush(out, cur, sl, lo, hi);
                lo = make_float4(0.f, 0.f, 0.f, 0.f);
                hi = make_float4(0.f, 0.f, 0.f, 0.f);
                cur = m0.z;
            }
            uint4 p0 = hh[(size_t)m0.x * 16 + sl];
            seg_acc(lo, hi, p0, __int_as_float(m0.y));
            e += 1;
            continue;
        }
        int4 m0 = g_edge4[e];
        if (m0.z != cur) {
            seg_flush(out, cur, sl, lo, hi);
            lo = make_float4(0.f, 0.f, 0.f, 0.f);
            hi = make_float4(0.f, 0.f, 0.f, 0.f);
            cur = m0.z;
        }
        uint4 p0 = hh[(size_t)m0.x * 16 + sl];
        seg_acc(lo, hi, p0, __int_as_float(m0.y));
        e += 1;
    }
    seg_flush(out, cur, sl, lo, hi);
}

// ---------------------------------------------------------------------------
extern "C" void kernel_launch(void* const* d_in, const int* in_sizes, int n_in,
                              void* d_out, int out_size) {
    const float* x    = (const float*)d_in[0];
    const float* W    = (const float*)d_in[1];
    const int*   erow = (const int*)  d_in[2];
    const int*   ecol = (const int*)  d_in[3];
    const float* eval = (const float*)d_in[4];
    float*       out  = (float*)d_out;

    int n_nodes = in_sizes[0] / DIM;
    int n_edges = in_sizes[2];

    static cudaStream_t s2 = nullptr;
    static cudaEvent_t  ev_fork = nullptr, ev_join = nullptr;
    if (!s2) {
        cudaStreamCreate(&s2);
        cudaEventCreateWithFlags(&ev_fork, cudaEventDisableTiming);
        cudaEventCreateWithFlags(&ev_join, cudaEventDisableTiming);
    }

    // Fork: memset(out) + GEMM path on s2 (shorter branch -> both free)
    cudaEventRecord(ev_fork, 0);
    cudaStreamWaitEvent(s2, ev_fork, 0);
    cudaMemsetAsync(d_out, 0, (size_t)out_size * sizeof(float), s2);
    k_prep_w<<<(DIM * DIM + 255) / 256, 256, 0, s2>>>(W);
    k_gemm<<<(n_nodes + 31) / 32, 256, 0, s2>>>(x);
    cudaEventRecord(ev_join, s2);

    // Binning path on the main (capture) stream
    k_zero_cnt<<<(N_NODES + 255) / 256, 256>>>();
    {
        int e4 = n_edges >> 2;
        int nt = e4 + (n_edges - e4 * 4);
        k_hist<<<(nt + 255) / 256, 256>>>(erow, n_edges);
    }
    k_scan1<<<N_CHUNKS, SCAN_CHUNK>>>();
    k_scan2<<<1, 256>>>();
    k_scan3<<<(N_NODES + 255) / 256, 256>>>(n_edges);
    {
        int e4 = n_edges >> 2;
        int nt = e4 + (n_edges - e4 * 4);
        k_place<<<(nt + 255) / 256, 256>>>(erow, ecol, eval, n_edges);
    }

    // Join: scatter needs g_h + zeroed out (s2) and g_edge4 (main)
    cudaStreamWaitEvent(0, ev_join, 0);
    {
        int ngrp   = (n_edges + ECHUNK - 1) / ECHUNK;
        int blocks = (ngrp + 7) / 8;
        k_segscatter<<<blocks, 128>>>(out, n_edges);
    }
}

// round 10
// speedup vs baseline: 1.0993x; 1.0993x over previous
#include <cuda_runtime.h>
#include <cuda_bf16.h>
#include <cuda_fp16.h>

#define N_NODES 100000
#define DIM 128
#define ROW_CAP 96            // bucket capacity; Poisson(16) max over 100K rows ~45

// ---------------------------------------------------------------------------
// Scratch (allocation-free rule: device globals)
// ---------------------------------------------------------------------------
__device__ __half g_h[N_NODES * DIM];          // h = x @ W^T  (fp16)
__device__ __half g_Wh[DIM * DIM];             // W in fp16
__device__ int    g_rowcnt[N_NODES];           // per-row append cursor
__device__ int2   g_edge[(size_t)N_NODES * ROW_CAP];   // {col, val-bits} buckets

// ---------------------------------------------------------------------------
__global__ void k_prep_w(const float* __restrict__ W) {
    int idx = blockIdx.x * blockDim.x + threadIdx.x;
    if (idx < DIM * DIM) g_Wh[idx] = __float2half_rn(W[idx]);
}

// ---------------------------------------------------------------------------
// GEMM via HMMA (unchanged — proven, hidden under the other branch)
// ---------------------------------------------------------------------------
#define SSTRIDE 136

__global__ void __launch_bounds__(256) k_gemm(const float* __restrict__ x) {
    __shared__ __half sA[32 * SSTRIDE];
    __shared__ __half sB[DIM * SSTRIDE];

    const int tid  = threadIdx.x;
    const int row0 = blockIdx.x * 32;

    const uint4* w4 = reinterpret_cast<const uint4*>(g_Wh);
    #pragma unroll
    for (int i = tid; i < 2048; i += 256) {
        int r = i >> 4, cg = i & 15;
        *reinterpret_cast<uint4*>(&sB[r * SSTRIDE + cg * 8]) = w4[i];
    }
    const float4* x4 = reinterpret_cast<const float4*>(x + (size_t)row0 * DIM);
    #pragma unroll
    for (int i = tid; i < 1024; i += 256) {
        float4 v = x4[i];
        int r = i >> 5, k4 = i & 31;
        __half2 p0 = __floats2half2_rn(v.x, v.y);
        __half2 p1 = __floats2half2_rn(v.z, v.w);
        __half* d = &sA[r * SSTRIDE + k4 * 4];
        *reinterpret_cast<__half2*>(d)     = p0;
        *reinterpret_cast<__half2*>(d + 2) = p1;
    }
    __syncthreads();

    const int warp = tid >> 5, lane = tid & 31;
    const int wr = (warp & 1) * 16;
    const int wc = (warp >> 1) * 32;
    const int qr = lane >> 2, qc = lane & 3;

    float c[4][4];
    #pragma unroll
    for (int nc = 0; nc < 4; nc++)
        #pragma unroll
        for (int j = 0; j < 4; j++) c[nc][j] = 0.f;

    #pragma unroll
    for (int ks = 0; ks < 8; ks++) {
        const int k0 = ks * 16 + qc * 2;
        const __half* A0 = &sA[(wr + qr) * SSTRIDE + k0];
        const __half* A8 = A0 + 8 * SSTRIDE;
        unsigned a0 = *reinterpret_cast<const unsigned*>(A0);
        unsigned a1 = *reinterpret_cast<const unsigned*>(A8);
        unsigned a2 = *reinterpret_cast<const unsigned*>(A0 + 8);
        unsigned a3 = *reinterpret_cast<const unsigned*>(A8 + 8);
        #pragma unroll
        for (int nc = 0; nc < 4; nc++) {
            const int n = wc + nc * 8 + qr;
            const __half* B0 = &sB[n * SSTRIDE + k0];
            unsigned b0 = *reinterpret_cast<const unsigned*>(B0);
            unsigned b1 = *reinterpret_cast<const unsigned*>(B0 + 8);
            asm("mma.sync.aligned.m16n8k16.row.col.f32.f16.f16.f32 "
                "{%0,%1,%2,%3}, {%4,%5,%6,%7}, {%8,%9}, {%0,%1,%2,%3};"
                : "+f"(c[nc][0]), "+f"(c[nc][1]), "+f"(c[nc][2]), "+f"(c[nc][3])
                : "r"(a0), "r"(a1), "r"(a2), "r"(a3), "r"(b0), "r"(b1));
        }
    }

    const int r0g = row0 + wr + qr;
    #pragma unroll
    for (int nc = 0; nc < 4; nc++) {
        const int col = wc + nc * 8 + qc * 2;
        __half2 lo = __floats2half2_rn(c[nc][0], c[nc][1]);
        __half2 hi = __floats2half2_rn(c[nc][2], c[nc][3]);
        *reinterpret_cast<__half2*>(&g_h[(size_t)r0g * DIM + col])       = lo;
        *reinterpret_cast<__half2*>(&g_h[(size_t)(r0g + 8) * DIM + col]) = hi;
    }
}

// ---------------------------------------------------------------------------
__global__ void k_zero_cnt() {
    int i = blockIdx.x * blockDim.x + threadIdx.x;
    if (i < N_NODES) g_rowcnt[i] = 0;
}

// Place: append edges into per-row buckets (no hist/scan needed).
// 4 edges per thread, vectorized input loads.
__global__ void k_place(const int*   __restrict__ erow,
                        const int*   __restrict__ ecol,
                        const float* __restrict__ eval,
                        int n_edges) {
    int t  = blockIdx.x * blockDim.x + threadIdx.x;
    int e4 = n_edges >> 2;
    if (t < e4) {
        int4   r = reinterpret_cast<const int4*>(erow)[t];
        int4   c = reinterpret_cast<const int4*>(ecol)[t];
        float4 v = reinterpret_cast<const float4*>(eval)[t];
        int p0 = atomicAdd(&g_rowcnt[r.x], 1);
        int p1 = atomicAdd(&g_rowcnt[r.y], 1);
        int p2 = atomicAdd(&g_rowcnt[r.z], 1);
        int p3 = atomicAdd(&g_rowcnt[r.w], 1);
        if (p0 < ROW_CAP) g_edge[(size_t)r.x * ROW_CAP + p0] = make_int2(c.x, __float_as_int(v.x));
        if (p1 < ROW_CAP) g_edge[(size_t)r.y * ROW_CAP + p1] = make_int2(c.y, __float_as_int(v.y));
        if (p2 < ROW_CAP) g_edge[(size_t)r.z * ROW_CAP + p2] = make_int2(c.z, __float_as_int(v.z));
        if (p3 < ROW_CAP) g_edge[(size_t)r.w * ROW_CAP + p3] = make_int2(c.w, __float_as_int(v.w));
    } else {
        int e = e4 * 4 + (t - e4);
        if (e < n_edges) {
            int r = erow[e];
            int pos = atomicAdd(&g_rowcnt[r], 1);
            if (pos < ROW_CAP) g_edge[(size_t)r * ROW_CAP + pos] = make_int2(ecol[e], __float_as_int(eval[e]));
        }
    }
}

// ---------------------------------------------------------------------------
// Rowgather (round-8 proven structure): 16 lanes per output row, LDG.128
// gathers, MLP=8, fp32 accumulate, coalesced non-atomic store.
// ---------------------------------------------------------------------------
__device__ __forceinline__ void acc_edge16(float4& aLo, float4& aHi, uint4 p, float v) {
    float2 f0 = __half22float2(*reinterpret_cast<__half2*>(&p.x));
    float2 f1 = __half22float2(*reinterpret_cast<__half2*>(&p.y));
    float2 f2 = __half22float2(*reinterpret_cast<__half2*>(&p.z));
    float2 f3 = __half22float2(*reinterpret_cast<__half2*>(&p.w));
    aLo.x += v * f0.x; aLo.y += v * f0.y; aLo.z += v * f1.x; aLo.w += v * f1.y;
    aHi.x += v * f2.x; aHi.y += v * f2.y; aHi.z += v * f3.x; aHi.w += v * f3.y;
}

__global__ void __launch_bounds__(128) k_rowgather(float* __restrict__ out) {
    int grp = blockIdx.x * 8 + (threadIdx.x >> 4);   // 16-lane group = one row
    int sl  = threadIdx.x & 15;
    if (grp >= N_NODES) return;

    int cnt = __ldg(&g_rowcnt[grp]);
    if (cnt > ROW_CAP) cnt = ROW_CAP;
    const int2* ep = &g_edge[(size_t)grp * ROW_CAP];

    const uint4* hh = reinterpret_cast<const uint4*>(g_h);   // 16 x 16B per row

    float4 l0 = make_float4(0.f,0.f,0.f,0.f), h0 = make_float4(0.f,0.f,0.f,0.f);
    float4 l1 = make_float4(0.f,0.f,0.f,0.f), h1 = make_float4(0.f,0.f,0.f,0.f);

    int i = 0;
    for (; i + 8 <= cnt; i += 8) {
        int2 e0 = ep[i + 0];
        int2 e1 = ep[i + 1];
        int2 e2 = ep[i + 2];
        int2 e3 = ep[i + 3];
        int2 e4 = ep[i + 4];
        int2 e5 = ep[i + 5];
        int2 e6 = ep[i + 6];
        int2 e7 = ep[i + 7];
        uint4 p0 = hh[(size_t)e0.x * 16 + sl];
        uint4 p1 = hh[(size_t)e1.x * 16 + sl];
        uint4 p2 = hh[(size_t)e2.x * 16 + sl];
        uint4 p3 = hh[(size_t)e3.x * 16 + sl];
        uint4 p4 = hh[(size_t)e4.x * 16 + sl];
        uint4 p5 = hh[(size_t)e5.x * 16 + sl];
        uint4 p6 = hh[(size_t)e6.x * 16 + sl];
        uint4 p7 = hh[(size_t)e7.x * 16 + sl];
        acc_edge16(l0, h0, p0, __int_as_float(e0.y));
        acc_edge16(l1, h1, p1, __int_as_float(e1.y));
        acc_edge16(l0, h0, p2, __int_as_float(e2.y));
        acc_edge16(l1, h1, p3, __int_as_float(e3.y));
        acc_edge16(l0, h0, p4, __int_as_float(e4.y));
        acc_edge16(l1, h1, p5, __int_as_float(e5.y));
        acc_edge16(l0, h0, p6, __int_as_float(e6.y));
        acc_edge16(l1, h1, p7, __int_as_float(e7.y));
    }
    for (; i + 2 <= cnt; i += 2) {
        int2 e0 = ep[i + 0];
        int2 e1 = ep[i + 1];
        uint4 p0 = hh[(size_t)e0.x * 16 + sl];
        uint4 p1 = hh[(size_t)e1.x * 16 + sl];
        acc_edge16(l0, h0, p0, __int_as_float(e0.y));
        acc_edge16(l1, h1, p1, __int_as_float(e1.y));
    }
    if (i < cnt) {
        int2 e0 = ep[i];
        uint4 p0 = hh[(size_t)e0.x * 16 + sl];
        acc_edge16(l0, h0, p0, __int_as_float(e0.y));
    }

    float4 lo = make_float4(l0.x + l1.x, l0.y + l1.y, l0.z + l1.z, l0.w + l1.w);
    float4 hi = make_float4(h0.x + h1.x, h0.y + h1.y, h0.z + h1.z, h0.w + h1.w);

    float* op = out + (size_t)grp * DIM + sl * 8;
    *reinterpret_cast<float4*>(op)     = lo;
    *reinterpret_cast<float4*>(op + 4) = hi;
}

// ---------------------------------------------------------------------------
extern "C" void kernel_launch(void* const* d_in, const int* in_sizes, int n_in,
                              void* d_out, int out_size) {
    const float* x    = (const float*)d_in[0];
    const float* W    = (const float*)d_in[1];
    const int*   erow = (const int*)  d_in[2];
    const int*   ecol = (const int*)  d_in[3];
    const float* eval = (const float*)d_in[4];
    float*       out  = (float*)d_out;

    int n_nodes = in_sizes[0] / DIM;
    int n_edges = in_sizes[2];

    static cudaStream_t s2 = nullptr;
    static cudaEvent_t  ev_fork = nullptr, ev_join = nullptr;
    if (!s2) {
        cudaStreamCreate(&s2);
        cudaEventCreateWithFlags(&ev_fork, cudaEventDisableTiming);
        cudaEventCreateWithFlags(&ev_join, cudaEventDisableTiming);
    }

    // Fork: GEMM branch on s2 (prep + gemm ~17us)
    cudaEventRecord(ev_fork, 0);
    cudaStreamWaitEvent(s2, ev_fork, 0);
    k_prep_w<<<(DIM * DIM + 255) / 256, 256, 0, s2>>>(W);
    k_gemm<<<(n_nodes + 31) / 32, 256, 0, s2>>>(x);
    cudaEventRecord(ev_join, s2);

    // Binning branch on main stream: zero cursors + bucket-append (~19us).
    // No hist, no scans.
    k_zero_cnt<<<(N_NODES + 255) / 256, 256>>>();
    {
        int e4 = n_edges >> 2;
        int nt = e4 + (n_edges - e4 * 4);
        k_place<<<(nt + 255) / 256, 256>>>(erow, ecol, eval, n_edges);
    }

    // Join: rowgather needs g_h (s2) and g_edge/g_rowcnt (main).
    // Writes every output row fully -> no memset of out needed.
    cudaStreamWaitEvent(0, ev_join, 0);
    k_rowgather<<<(N_NODES + 7) / 8, 128>>>(out);
}

// round 11
// speedup vs baseline: 1.1288x; 1.0269x over previous
#include <cuda_runtime.h>
#include <cuda_bf16.h>
#include <cuda_fp16.h>

#define N_NODES 100000
#define DIM 128
#define ROW_CAP 32            // bucket capacity: 25.6MB region, L2-resident
#define OV_CAP 65536          // overflow capacity (expected ~30-100 edges)

// ---------------------------------------------------------------------------
// Scratch (allocation-free rule: device globals)
// ---------------------------------------------------------------------------
__device__ __half g_h[N_NODES * DIM];                  // h = x @ W^T  (fp16)
__device__ __half g_Wh[DIM * DIM];                     // W in fp16
__device__ int    g_rowcnt[N_NODES];                   // per-row append cursor
__device__ int2   g_edge[(size_t)N_NODES * ROW_CAP];   // {col, val-bits} buckets
__device__ int    g_ovcnt;                             // overflow edge count
__device__ int4   g_ovedge[OV_CAP];                    // {col, val-bits, row, 0}

// ---------------------------------------------------------------------------
__global__ void k_prep_w(const float* __restrict__ W) {
    int idx = blockIdx.x * blockDim.x + threadIdx.x;
    if (idx < DIM * DIM) g_Wh[idx] = __float2half_rn(W[idx]);
}

// ---------------------------------------------------------------------------
// GEMM via HMMA (unchanged — proven, hidden under the other branch)
// ---------------------------------------------------------------------------
#define SSTRIDE 136

__global__ void __launch_bounds__(256) k_gemm(const float* __restrict__ x) {
    __shared__ __half sA[32 * SSTRIDE];
    __shared__ __half sB[DIM * SSTRIDE];

    const int tid  = threadIdx.x;
    const int row0 = blockIdx.x * 32;

    const uint4* w4 = reinterpret_cast<const uint4*>(g_Wh);
    #pragma unroll
    for (int i = tid; i < 2048; i += 256) {
        int r = i >> 4, cg = i & 15;
        *reinterpret_cast<uint4*>(&sB[r * SSTRIDE + cg * 8]) = w4[i];
    }
    const float4* x4 = reinterpret_cast<const float4*>(x + (size_t)row0 * DIM);
    #pragma unroll
    for (int i = tid; i < 1024; i += 256) {
        float4 v = x4[i];
        int r = i >> 5, k4 = i & 31;
        __half2 p0 = __floats2half2_rn(v.x, v.y);
        __half2 p1 = __floats2half2_rn(v.z, v.w);
        __half* d = &sA[r * SSTRIDE + k4 * 4];
        *reinterpret_cast<__half2*>(d)     = p0;
        *reinterpret_cast<__half2*>(d + 2) = p1;
    }
    __syncthreads();

    const int warp = tid >> 5, lane = tid & 31;
    const int wr = (warp & 1) * 16;
    const int wc = (warp >> 1) * 32;
    const int qr = lane >> 2, qc = lane & 3;

    float c[4][4];
    #pragma unroll
    for (int nc = 0; nc < 4; nc++)
        #pragma unroll
        for (int j = 0; j < 4; j++) c[nc][j] = 0.f;

    #pragma unroll
    for (int ks = 0; ks < 8; ks++) {
        const int k0 = ks * 16 + qc * 2;
        const __half* A0 = &sA[(wr + qr) * SSTRIDE + k0];
        const __half* A8 = A0 + 8 * SSTRIDE;
        unsigned a0 = *reinterpret_cast<const unsigned*>(A0);
        unsigned a1 = *reinterpret_cast<const unsigned*>(A8);
        unsigned a2 = *reinterpret_cast<const unsigned*>(A0 + 8);
        unsigned a3 = *reinterpret_cast<const unsigned*>(A8 + 8);
        #pragma unroll
        for (int nc = 0; nc < 4; nc++) {
            const int n = wc + nc * 8 + qr;
            const __half* B0 = &sB[n * SSTRIDE + k0];
            unsigned b0 = *reinterpret_cast<const unsigned*>(B0);
            unsigned b1 = *reinterpret_cast<const unsigned*>(B0 + 8);
            asm("mma.sync.aligned.m16n8k16.row.col.f32.f16.f16.f32 "
                "{%0,%1,%2,%3}, {%4,%5,%6,%7}, {%8,%9}, {%0,%1,%2,%3};"
                : "+f"(c[nc][0]), "+f"(c[nc][1]), "+f"(c[nc][2]), "+f"(c[nc][3])
                : "r"(a0), "r"(a1), "r"(a2), "r"(a3), "r"(b0), "r"(b1));
        }
    }

    const int r0g = row0 + wr + qr;
    #pragma unroll
    for (int nc = 0; nc < 4; nc++) {
        const int col = wc + nc * 8 + qc * 2;
        __half2 lo = __floats2half2_rn(c[nc][0], c[nc][1]);
        __half2 hi = __floats2half2_rn(c[nc][2], c[nc][3]);
        *reinterpret_cast<__half2*>(&g_h[(size_t)r0g * DIM + col])       = lo;
        *reinterpret_cast<__half2*>(&g_h[(size_t)(r0g + 8) * DIM + col]) = hi;
    }
}

// ---------------------------------------------------------------------------
__global__ void k_zero_cnt() {
    int i = blockIdx.x * blockDim.x + threadIdx.x;
    if (i < N_NODES) g_rowcnt[i] = 0;
    if (i == 0) g_ovcnt = 0;
}

// Place: append edges into per-row buckets; rare overflow -> side list.
__global__ void k_place(const int*   __restrict__ erow,
                        const int*   __restrict__ ecol,
                        const float* __restrict__ eval,
                        int n_edges) {
    int t  = blockIdx.x * blockDim.x + threadIdx.x;
    int e4 = n_edges >> 2;
    if (t < e4) {
        int4   r = reinterpret_cast<const int4*>(erow)[t];
        int4   c = reinterpret_cast<const int4*>(ecol)[t];
        float4 v = reinterpret_cast<const float4*>(eval)[t];
        int rr[4] = {r.x, r.y, r.z, r.w};
        int cc[4] = {c.x, c.y, c.z, c.w};
        float vv[4] = {v.x, v.y, v.z, v.w};
        #pragma unroll
        for (int j = 0; j < 4; j++) {
            int pos = atomicAdd(&g_rowcnt[rr[j]], 1);
            if (pos < ROW_CAP) {
                g_edge[(size_t)rr[j] * ROW_CAP + pos] = make_int2(cc[j], __float_as_int(vv[j]));
            } else {
                int oi = atomicAdd(&g_ovcnt, 1);
                if (oi < OV_CAP) g_ovedge[oi] = make_int4(cc[j], __float_as_int(vv[j]), rr[j], 0);
            }
        }
    } else {
        int e = e4 * 4 + (t - e4);
        if (e < n_edges) {
            int r = erow[e];
            int pos = atomicAdd(&g_rowcnt[r], 1);
            if (pos < ROW_CAP) {
                g_edge[(size_t)r * ROW_CAP + pos] = make_int2(ecol[e], __float_as_int(eval[e]));
            } else {
                int oi = atomicAdd(&g_ovcnt, 1);
                if (oi < OV_CAP) g_ovedge[oi] = make_int4(ecol[e], __float_as_int(eval[e]), r, 0);
            }
        }
    }
}

// ---------------------------------------------------------------------------
// Rowgather: 16 lanes per output row, LDG.128 gathers, MLP=8, fp32 accum,
// coalesced non-atomic store. (R8 proven structure, bucket-fed.)
// ---------------------------------------------------------------------------
__device__ __forceinline__ void acc_edge16(float4& aLo, float4& aHi, uint4 p, float v) {
    float2 f0 = __half22float2(*reinterpret_cast<__half2*>(&p.x));
    float2 f1 = __half22float2(*reinterpret_cast<__half2*>(&p.y));
    float2 f2 = __half22float2(*reinterpret_cast<__half2*>(&p.z));
    float2 f3 = __half22float2(*reinterpret_cast<__half2*>(&p.w));
    aLo.x += v * f0.x; aLo.y += v * f0.y; aLo.z += v * f1.x; aLo.w += v * f1.y;
    aHi.x += v * f2.x; aHi.y += v * f2.y; aHi.z += v * f3.x; aHi.w += v * f3.y;
}

__global__ void __launch_bounds__(128) k_rowgather(float* __restrict__ out) {
    int grp = blockIdx.x * 8 + (threadIdx.x >> 4);   // 16-lane group = one row
    int sl  = threadIdx.x & 15;
    if (grp >= N_NODES) return;

    int cnt = __ldg(&g_rowcnt[grp]);
    if (cnt > ROW_CAP) cnt = ROW_CAP;
    const int2* ep = &g_edge[(size_t)grp * ROW_CAP];

    const uint4* hh = reinterpret_cast<const uint4*>(g_h);   // 16 x 16B per row

    float4 l0 = make_float4(0.f,0.f,0.f,0.f), h0 = make_float4(0.f,0.f,0.f,0.f);
    float4 l1 = make_float4(0.f,0.f,0.f,0.f), h1 = make_float4(0.f,0.f,0.f,0.f);

    int i = 0;
    for (; i + 8 <= cnt; i += 8) {
        int2 e0 = ep[i + 0];
        int2 e1 = ep[i + 1];
        int2 e2 = ep[i + 2];
        int2 e3 = ep[i + 3];
        int2 e4 = ep[i + 4];
        int2 e5 = ep[i + 5];
        int2 e6 = ep[i + 6];
        int2 e7 = ep[i + 7];
        uint4 p0 = hh[(size_t)e0.x * 16 + sl];
        uint4 p1 = hh[(size_t)e1.x * 16 + sl];
        uint4 p2 = hh[(size_t)e2.x * 16 + sl];
        uint4 p3 = hh[(size_t)e3.x * 16 + sl];
        uint4 p4 = hh[(size_t)e4.x * 16 + sl];
        uint4 p5 = hh[(size_t)e5.x * 16 + sl];
        uint4 p6 = hh[(size_t)e6.x * 16 + sl];
        uint4 p7 = hh[(size_t)e7.x * 16 + sl];
        acc_edge16(l0, h0, p0, __int_as_float(e0.y));
        acc_edge16(l1, h1, p1, __int_as_float(e1.y));
        acc_edge16(l0, h0, p2, __int_as_float(e2.y));
        acc_edge16(l1, h1, p3, __int_as_float(e3.y));
        acc_edge16(l0, h0, p4, __int_as_float(e4.y));
        acc_edge16(l1, h1, p5, __int_as_float(e5.y));
        acc_edge16(l0, h0, p6, __int_as_float(e6.y));
        acc_edge16(l1, h1, p7, __int_as_float(e7.y));
    }
    for (; i + 2 <= cnt; i += 2) {
        int2 e0 = ep[i + 0];
        int2 e1 = ep[i + 1];
        uint4 p0 = hh[(size_t)e0.x * 16 + sl];
        uint4 p1 = hh[(size_t)e1.x * 16 + sl];
        acc_edge16(l0, h0, p0, __int_as_float(e0.y));
        acc_edge16(l1, h1, p1, __int_as_float(e1.y));
    }
    if (i < cnt) {
        int2 e0 = ep[i];
        uint4 p0 = hh[(size_t)e0.x * 16 + sl];
        acc_edge16(l0, h0, p0, __int_as_float(e0.y));
    }

    float4 lo = make_float4(l0.x + l1.x, l0.y + l1.y, l0.z + l1.z, l0.w + l1.w);
    float4 hi = make_float4(h0.x + h1.x, h0.y + h1.y, h0.z + h1.z, h0.w + h1.w);

    float* op = out + (size_t)grp * DIM + sl * 8;
    *reinterpret_cast<float4*>(op)     = lo;
    *reinterpret_cast<float4*>(op + 4) = hi;
}

// ---------------------------------------------------------------------------
// Overflow cleanup: grid-stride over overflow edges (expected ~30-100),
// vec4 red-atomics onto the already-written out rows.
// ---------------------------------------------------------------------------
__global__ void __launch_bounds__(256) k_overflow(float* __restrict__ out) {
    int n = g_ovcnt;                 // uniform load; 0 or tiny
    if (n > OV_CAP) n = OV_CAP;
    int sl    = threadIdx.x & 15;
    int grp0  = blockIdx.x * 16 + (threadIdx.x >> 4);
    int nGrps = gridDim.x * 16;

    const uint4* hh = reinterpret_cast<const uint4*>(g_h);
    for (int g = grp0; g < n; g += nGrps) {
        int4 m = g_ovedge[g];
        float v = __int_as_float(m.y);
        uint4 p = hh[(size_t)m.x * 16 + sl];
        float2 f0 = __half22float2(*reinterpret_cast<__half2*>(&p.x));
        float2 f1 = __half22float2(*reinterpret_cast<__half2*>(&p.y));
        float2 f2 = __half22float2(*reinterpret_cast<__half2*>(&p.z));
        float2 f3 = __half22float2(*reinterpret_cast<__half2*>(&p.w));
        float* op = out + (size_t)m.z * DIM + sl * 8;
        asm volatile("red.global.add.v4.f32 [%0], {%1,%2,%3,%4};"
                     :: "l"(op), "f"(v * f0.x), "f"(v * f0.y),
                        "f"(v * f1.x), "f"(v * f1.y) : "memory");
        asm volatile("red.global.add.v4.f32 [%0], {%1,%2,%3,%4};"
                     :: "l"(op + 4), "f"(v * f2.x), "f"(v * f2.y),
                        "f"(v * f3.x), "f"(v * f3.y) : "memory");
    }
}

// ---------------------------------------------------------------------------
extern "C" void kernel_launch(void* const* d_in, const int* in_sizes, int n_in,
                              void* d_out, int out_size) {
    const float* x    = (const float*)d_in[0];
    const float* W    = (const float*)d_in[1];
    const int*   erow = (const int*)  d_in[2];
    const int*   ecol = (const int*)  d_in[3];
    const float* eval = (const float*)d_in[4];
    float*       out  = (float*)d_out;

    int n_nodes = in_sizes[0] / DIM;
    int n_edges = in_sizes[2];

    static cudaStream_t s2 = nullptr;
    static cudaEvent_t  ev_fork = nullptr, ev_join = nullptr;
    if (!s2) {
        cudaStreamCreate(&s2);
        cudaEventCreateWithFlags(&ev_fork, cudaEventDisableTiming);
        cudaEventCreateWithFlags(&ev_join, cudaEventDisableTiming);
    }

    // Fork: GEMM branch on s2 (prep + gemm ~17us)
    cudaEventRecord(ev_fork, 0);
    cudaStreamWaitEvent(s2, ev_fork, 0);
    k_prep_w<<<(DIM * DIM + 255) / 256, 256, 0, s2>>>(W);
    k_gemm<<<(n_nodes + 31) / 32, 256, 0, s2>>>(x);
    cudaEventRecord(ev_join, s2);

    // Binning branch on main stream: zero cursors + bucket-append (~18us)
    k_zero_cnt<<<(N_NODES + 255) / 256, 256>>>();
    {
        int e4 = n_edges >> 2;
        int nt = e4 + (n_edges - e4 * 4);
        k_place<<<(nt + 255) / 256, 256>>>(erow, ecol, eval, n_edges);
    }

    // Join: rowgather needs g_h (s2) and buckets (main). Writes every row.
    cudaStreamWaitEvent(0, ev_join, 0);
    k_rowgather<<<(N_NODES + 7) / 8, 128>>>(out);

    // Overflow edges (expected ~0-100) added atomically after the stores.
    k_overflow<<<64, 256>>>(out);
}